// round 16
// baseline (speedup 1.0000x reference)
#include <cuda_runtime.h>
#include <cuda_fp16.h>

#define HID 128
#define NS  12
#define NW  14
#define PAIRS (NW/2)
#define THREADS (NW*32)
#define GRID 148
#define MROWS 16

typedef unsigned u32;
typedef unsigned short u16;

// ---- SMEM layout (bytes) ----
#define OFF_W1F 0
#define OFF_W1B 32768
#define OFF_W2F 65536
#define OFF_W2B 98304
#define OFF_W0F 131072
#define OFF_W0B 135168
#define OFF_CON 139264
#define OFF_PB  141568
#define PBSTRIDE 8256                // ACTa 4096 | ACTb 4096 | VX 64
#define SMEM_BYTES (OFF_PB + PAIRS*PBSTRIDE)   // 199360
// init-time aliases inside PB region: Wh staging 32KB @ +0, PRT @ +32768

// tanh.approx.f32: 1 MUFU op, err ~2^-11 (same order as fp16 rounding)
__device__ __forceinline__ float ftanh(float x)
{
    float y;
    asm("tanh.approx.f32 %0, %1;" : "=f"(y) : "f"(x));
    return y;
}
__device__ __forceinline__ u32 f2h2(float a, float b)
{
    __half2 h = __floats2half2_rn(a, b);
    return *(u32*)&h;
}
__device__ __forceinline__ float2 h22f2(u32 u)
{
    return __half22float2(*(__half2*)&u);
}
__device__ __forceinline__ u32 packh(u16 lo, u16 hi)
{
    return (u32)lo | ((u32)hi << 16);
}
__device__ __forceinline__ void mma16816(float c[4], const u32* a, uint2 b)
{
    asm volatile(
        "mma.sync.aligned.m16n8k16.row.col.f32.f16.f16.f32 "
        "{%0,%1,%2,%3}, {%4,%5,%6,%7}, {%8,%9}, {%0,%1,%2,%3};\n"
        : "+f"(c[0]), "+f"(c[1]), "+f"(c[2]), "+f"(c[3])
        : "r"(a[0]), "r"(a[1]), "r"(a[2]), "r"(a[3]), "r"(b.x), "r"(b.y));
}
__device__ __forceinline__ void bar_pair(int id)
{
    asm volatile("bar.sync %0, 64;" :: "r"(id) : "memory");
}

__global__ __launch_bounds__(THREADS, 1)
void mlp_kernel(const float* __restrict__ state,
                const float* __restrict__ safe_m, const float* __restrict__ safe_l,
                const float* __restrict__ W0, const float* __restrict__ b0,
                const float* __restrict__ W1, const float* __restrict__ b1,
                const float* __restrict__ W2, const float* __restrict__ b2,
                const float* __restrict__ W3, const float* __restrict__ b3,
                const float* __restrict__ Wout, const float* __restrict__ bout,
                float* __restrict__ out, int nb)
{
    extern __shared__ char smem[];
    uint2* W1F = (uint2*)(smem + OFF_W1F);
    uint2* W1B = (uint2*)(smem + OFF_W1B);
    uint2* W2F = (uint2*)(smem + OFF_W2F);
    uint2* W2B = (uint2*)(smem + OFF_W2B);
    uint2* W0F = (uint2*)(smem + OFF_W0F);
    uint2* W0B = (uint2*)(smem + OFF_W0B);
    float* CON = (float*)(smem + OFF_CON);
    u32*  WhU  = (u32*)(smem + OFF_PB);        // fp16 staging [128*128] (as 8192 u32)
    u16*  WhS  = (u16*)(smem + OFF_PB);
    float* PRT = (float*)(smem + OFF_PB + 32768);  // R3/c3 partials (512 floats)

    int tid = threadIdx.x;

    // ---- constants + R3 partials (coalesced) + W1 staging (coalesced) ----
    if (tid < HID) {
        CON[0   + tid] = b0[tid];
        CON[128 + tid] = b1[tid];
        CON[256 + tid] = b2[tid];
        PRT[384 + tid] = Wout[tid] * b3[tid];  // c3 partial
    }
    if (tid < NS) {
        float m = safe_m[tid], lo = safe_l[tid];
        CON[512 + tid] = 0.5f * (m + lo);
        CON[528 + tid] = 2.0f / (m - lo);
    }
    if (tid < 384) {   // R3 partials: 3 slices x 128 threads, coalesced rows
        int h = tid & 127, sl = tid >> 7;
        int j0 = (sl * HID) / 3, j1 = ((sl + 1) * HID) / 3;
        float acc = 0.f;
#pragma unroll 4
        for (int j = j0; j < j1; ++j) acc = fmaf(Wout[j], W3[j*HID + h], acc);
        PRT[sl*128 + h] = acc;
    }
    for (int i = tid; i < HID*HID/2; i += THREADS) {   // W1 -> fp16 SMEM, coalesced
        float2 wv = *(const float2*)&W1[2*i];
        WhU[i] = f2h2(wv.x, wv.y);
    }
    __syncthreads();

    // ---- build W1F/W1B from staged SMEM; combine R3/c3 ----
    for (int e = tid; e < 128*32; e += THREADS) {
        int T = e >> 5, lf = e & 31;
        int kt = T >> 4, nt = T & 15, qf = lf & 3, gf = lf >> 2;
        int n = 8*nt + gf, k = 16*kt + 2*qf;
        uint2 uf, ub;
        uf.x = WhU[(n*HID + k) >> 1];
        uf.y = WhU[(n*HID + k + 8) >> 1];
        ub.x = packh(WhS[k*HID + n],     WhS[(k+1)*HID + n]);
        ub.y = packh(WhS[(k+8)*HID + n], WhS[(k+9)*HID + n]);
        W1F[e] = uf; W1B[e] = ub;
    }
    if (tid < HID)
        CON[384 + tid] = PRT[tid] + PRT[128 + tid] + PRT[256 + tid];
    if (tid == 0) {
        float c = bout[0];
#pragma unroll 4
        for (int i = 0; i < HID; i += 4) {
            float4 p = *(const float4*)&PRT[384 + i];
            c += p.x + p.y + p.z + p.w;
        }
        CON[544] = c;
    }
    __syncthreads();

    // ---- stage W2 (coalesced), then build W2F/W2B + W0F/W0B ----
    for (int i = tid; i < HID*HID/2; i += THREADS) {
        float2 wv = *(const float2*)&W2[2*i];
        WhU[i] = f2h2(wv.x, wv.y);
    }
    __syncthreads();
    for (int e = tid; e < 128*32; e += THREADS) {
        int T = e >> 5, lf = e & 31;
        int kt = T >> 4, nt = T & 15, qf = lf & 3, gf = lf >> 2;
        int n = 8*nt + gf, k = 16*kt + 2*qf;
        uint2 uf, ub;
        uf.x = WhU[(n*HID + k) >> 1];
        uf.y = WhU[(n*HID + k + 8) >> 1];
        ub.x = packh(WhS[k*HID + n],     WhS[(k+1)*HID + n]);
        ub.y = packh(WhS[(k+8)*HID + n], WhS[(k+9)*HID + n]);
        W2F[e] = uf; W2B[e] = ub;
    }
    for (int e = tid; e < 16*32; e += THREADS) {
        int T = e >> 5, lf = e & 31, qf = lf & 3, gf = lf >> 2;
        {   // W0F: fwd GEMM0, T = nt
            int n = 8*T + gf, k = 2*qf;
            uint2 u;
            u.x = f2h2(W0[n*NS + k], W0[n*NS + k + 1]);
            u.y = (qf < 2) ? f2h2(W0[n*NS + k + 8], W0[n*NS + k + 9]) : 0u;
            W0F[e] = u;
        }
        {   // W0B: final J, kt=T>>1, nt=T&1
            int kt = T >> 1, ntb = T & 1;
            int n = 8*ntb + gf, k = 16*kt + 2*qf;
            float w00 = 0.f, w01 = 0.f, w10 = 0.f, w11 = 0.f;
            if (n < NS) {
                w00 = W0[k*NS + n];     w01 = W0[(k+1)*NS + n];
                w10 = W0[(k+8)*NS + n]; w11 = W0[(k+9)*NS + n];
            }
            uint2 u; u.x = f2h2(w00, w01); u.y = f2h2(w10, w11);
            W0B[e] = u;
        }
    }
    __syncthreads();

    int w = tid >> 5, l = tid & 31, q = l & 3, g = l >> 2;
    int pair = w >> 1, wa = w & 1;
    char* PB = smem + OFF_PB + pair*PBSTRIDE;
    uint2* ACTa = (uint2*)PB;             // [16 nt][32 lanes]
    uint2* ACTb = (uint2*)(PB + 4096);
    float* VX   = (float*)(PB + 8192);
    int barid = pair + 1;

    const float* B0S = CON;
    const float* B1S = CON + 128;
    const float* B2S = CON + 256;
    const float* R3S = CON + 384;
    const float* CENS = CON + 512;
    const float* INVS = CON + 528;

    int nt0 = 8*wa;                       // this warp's n-tile half

    int ntask = (nb + MROWS - 1) / MROWS;
    for (int task = blockIdx.x + GRID*pair; task < ntask; task += GRID*PAIRS) {
        int base = task * MROWS;
        int ra = base + g, rb = base + g + 8;
        bool oka = ra < nb, okb = rb < nb;

        u32 A[32];
        u32 V0k[16], V1k[16];             // own-half V0/V1 (fp16 pairs), register-resident
        float c[8][4];

        // ---- X load + normalize -> A[0..3] ----
        {
            float2 z2 = make_float2(0.f, 0.f);
            float2 xa = oka ? *(const float2*)&state[ra*NS + 2*q] : z2;
            float2 xb = okb ? *(const float2*)&state[rb*NS + 2*q] : z2;
            float2 xc = z2, xd = z2;
            float c0v = CENS[2*q], c1v = CENS[2*q+1];
            float i0v = INVS[2*q], i1v = INVS[2*q+1];
            xa.x = (xa.x - c0v)*i0v; xa.y = (xa.y - c1v)*i1v;
            xb.x = (xb.x - c0v)*i0v; xb.y = (xb.y - c1v)*i1v;
            if (q < 2) {
                if (oka) xc = *(const float2*)&state[ra*NS + 2*q + 8];
                if (okb) xd = *(const float2*)&state[rb*NS + 2*q + 8];
                float c2v = CENS[2*q+8], c3v = CENS[2*q+9];
                float i2v = INVS[2*q+8], i3v = INVS[2*q+9];
                xc.x = (xc.x - c2v)*i2v; xc.y = (xc.y - c3v)*i3v;
                xd.x = (xd.x - c2v)*i2v; xd.y = (xd.y - c3v)*i3v;
            }
            A[0] = f2h2(xa.x, xa.y);
            A[1] = f2h2(xb.x, xb.y);
            A[2] = f2h2(xc.x, xc.y);
            A[3] = f2h2(xd.x, xd.y);
        }

        // ---- G0: V0 = tanh(X*W0^T + b0) -> ACTa + V0k ----
#pragma unroll
        for (int i = 0; i < 8; ++i) {
            int nt = nt0 + i;
            float2 bp = *(const float2*)&B0S[8*nt + 2*q];
            c[i][0] = bp.x; c[i][1] = bp.y; c[i][2] = bp.x; c[i][3] = bp.y;
            mma16816(c[i], &A[0], W0F[nt*32 + l]);
        }
#pragma unroll
        for (int i = 0; i < 8; ++i) {
            uint2 u;
            u.x = f2h2(ftanh(c[i][0]), ftanh(c[i][1]));
            u.y = f2h2(ftanh(c[i][2]), ftanh(c[i][3]));
            ACTa[(nt0 + i)*32 + l] = u;
            V0k[2*i] = u.x; V0k[2*i+1] = u.y;
        }
        bar_pair(barid);                             // (1) ACTa complete

        // ---- G1: V1 = tanh(V0*W1^T + b1): read a -> write b + V1k ----
#pragma unroll
        for (int j = 0; j < 16; ++j) {
            uint2 v = ACTa[j*32 + l];
            A[2*j] = v.x; A[2*j+1] = v.y;
        }
#pragma unroll
        for (int i = 0; i < 8; ++i) {
            float2 bp = *(const float2*)&B1S[8*(nt0+i) + 2*q];
            c[i][0] = bp.x; c[i][1] = bp.y; c[i][2] = bp.x; c[i][3] = bp.y;
        }
#pragma unroll
        for (int kt = 0; kt < 8; ++kt)
#pragma unroll
            for (int i = 0; i < 8; ++i)
                mma16816(c[i], &A[kt*4], W1F[(kt*16 + nt0 + i)*32 + l]);
#pragma unroll
        for (int i = 0; i < 8; ++i) {
            uint2 u;
            u.x = f2h2(ftanh(c[i][0]), ftanh(c[i][1]));
            u.y = f2h2(ftanh(c[i][2]), ftanh(c[i][3]));
            ACTb[(nt0 + i)*32 + l] = u;
            V1k[2*i] = u.x; V1k[2*i+1] = u.y;
        }
        bar_pair(barid);                             // (2) ACTb complete

        // ---- G2: V2 = tanh(V1*W2^T + b2); vout partial; g2: read b -> write a ----
#pragma unroll
        for (int j = 0; j < 16; ++j) {
            uint2 v = ACTb[j*32 + l];
            A[2*j] = v.x; A[2*j+1] = v.y;
        }
#pragma unroll
        for (int i = 0; i < 8; ++i) {
            float2 bp = *(const float2*)&B2S[8*(nt0+i) + 2*q];
            c[i][0] = bp.x; c[i][1] = bp.y; c[i][2] = bp.x; c[i][3] = bp.y;
        }
#pragma unroll
        for (int kt = 0; kt < 8; ++kt)
#pragma unroll
            for (int i = 0; i < 8; ++i)
                mma16816(c[i], &A[kt*4], W2F[(kt*16 + nt0 + i)*32 + l]);
        float vg = 0.f, vg8 = 0.f;
#pragma unroll
        for (int i = 0; i < 8; ++i) {
            int nt = nt0 + i;
            float2 r3p = *(const float2*)&R3S[8*nt + 2*q];
            float t0 = ftanh(c[i][0]), t1 = ftanh(c[i][1]);
            float t2 = ftanh(c[i][2]), t3 = ftanh(c[i][3]);
            vg  += r3p.x*t0 + r3p.y*t1;
            vg8 += r3p.x*t2 + r3p.y*t3;
            uint2 u;
            u.x = f2h2(r3p.x*(1.f - t0*t0), r3p.y*(1.f - t1*t1));
            u.y = f2h2(r3p.x*(1.f - t2*t2), r3p.y*(1.f - t3*t3));
            ACTa[nt*32 + l] = u;
        }
        vg  += __shfl_xor_sync(0xffffffffu, vg, 1);
        vg  += __shfl_xor_sync(0xffffffffu, vg, 2);
        vg8 += __shfl_xor_sync(0xffffffffu, vg8, 1);
        vg8 += __shfl_xor_sync(0xffffffffu, vg8, 2);
        if (wa == 1 && q == 0) { VX[g] = vg; VX[8+g] = vg8; }
        bar_pair(barid);                             // (3) g2 + VX complete
        if (wa == 0 && q == 0) {
            float c3 = CON[544];
            if (oka) out[ra*13] = vg + VX[g] + c3;
            if (okb) out[rb*13] = vg8 + VX[8+g] + c3;
        }

        // ---- B2: r1 = g2*W2 ; g1 = r1*(1-V1^2): read a -> write b ----
#pragma unroll
        for (int j = 0; j < 16; ++j) {
            uint2 v = ACTa[j*32 + l];
            A[2*j] = v.x; A[2*j+1] = v.y;
        }
#pragma unroll
        for (int i = 0; i < 8; ++i) { c[i][0]=0.f; c[i][1]=0.f; c[i][2]=0.f; c[i][3]=0.f; }
#pragma unroll
        for (int kt = 0; kt < 8; ++kt)
#pragma unroll
            for (int i = 0; i < 8; ++i)
                mma16816(c[i], &A[kt*4], W2B[(kt*16 + nt0 + i)*32 + l]);
#pragma unroll
        for (int i = 0; i < 8; ++i) {
            float2 va = h22f2(V1k[2*i]), vb = h22f2(V1k[2*i+1]);
            uint2 u;
            u.x = f2h2(c[i][0]*(1.f - va.x*va.x), c[i][1]*(1.f - va.y*va.y));
            u.y = f2h2(c[i][2]*(1.f - vb.x*vb.x), c[i][3]*(1.f - vb.y*vb.y));
            ACTb[(nt0 + i)*32 + l] = u;
        }
        bar_pair(barid);                             // (4) g1 complete

        // ---- B1: r0 = g1*W1 ; g0 = r0*(1-V0^2): read b -> write a ----
#pragma unroll
        for (int j = 0; j < 16; ++j) {
            uint2 v = ACTb[j*32 + l];
            A[2*j] = v.x; A[2*j+1] = v.y;
        }
#pragma unroll
        for (int i = 0; i < 8; ++i) { c[i][0]=0.f; c[i][1]=0.f; c[i][2]=0.f; c[i][3]=0.f; }
#pragma unroll
        for (int kt = 0; kt < 8; ++kt)
#pragma unroll
            for (int i = 0; i < 8; ++i)
                mma16816(c[i], &A[kt*4], W1B[(kt*16 + nt0 + i)*32 + l]);
#pragma unroll
        for (int i = 0; i < 8; ++i) {
            float2 va = h22f2(V0k[2*i]), vb = h22f2(V0k[2*i+1]);
            uint2 u;
            u.x = f2h2(c[i][0]*(1.f - va.x*va.x), c[i][1]*(1.f - va.y*va.y));
            u.y = f2h2(c[i][2]*(1.f - vb.x*vb.x), c[i][3]*(1.f - vb.y*vb.y));
            ACTa[(nt0 + i)*32 + l] = u;
        }
        bar_pair(barid);                             // (5) g0 complete

        // ---- J: g0*W0 -> [16x12]; warp wa does n-tile wa: read a ----
#pragma unroll
        for (int j = 0; j < 16; ++j) {
            uint2 v = ACTa[j*32 + l];
            A[2*j] = v.x; A[2*j+1] = v.y;
        }
        {
            float cj[4] = {0.f, 0.f, 0.f, 0.f};
#pragma unroll
            for (int kt = 0; kt < 8; ++kt)
                mma16816(cj, &A[kt*4], W0B[(kt*2 + wa)*32 + l]);
            int cb = 8*wa + 2*q;
            if (cb < NS) {
                float iv0 = INVS[cb], iv1 = INVS[cb+1];
                if (oka) {
                    out[ra*13 + 1 + cb]     = cj[0]*iv0;
                    out[ra*13 + 1 + cb + 1] = cj[1]*iv1;
                }
                if (okb) {
                    out[rb*13 + 1 + cb]     = cj[2]*iv0;
                    out[rb*13 + 1 + cb + 1] = cj[3]*iv1;
                }
            }
        }
        bar_pair(barid);                             // (6) J reads done before next G0
    }
}

extern "C" void kernel_launch(void* const* d_in, const int* in_sizes, int n_in,
                              void* d_out, int out_size)
{
    const float* state  = (const float*)d_in[0];
    const float* safe_m = (const float*)d_in[1];
    const float* safe_l = (const float*)d_in[2];
    const float* W0     = (const float*)d_in[3];
    const float* b0     = (const float*)d_in[4];
    const float* W1     = (const float*)d_in[5];
    const float* b1     = (const float*)d_in[6];
    const float* W2     = (const float*)d_in[7];
    const float* b2     = (const float*)d_in[8];
    const float* W3     = (const float*)d_in[9];
    const float* b3     = (const float*)d_in[10];
    const float* Wout   = (const float*)d_in[11];
    const float* bout   = (const float*)d_in[12];
    float* out = (float*)d_out;

    int nb = in_sizes[0] / NS;

    cudaFuncSetAttribute(mlp_kernel, cudaFuncAttributeMaxDynamicSharedMemorySize,
                         SMEM_BYTES);

    mlp_kernel<<<GRID, THREADS, SMEM_BYTES>>>(
        state, safe_m, safe_l, W0, b0, W1, b1, W2, b2, W3, b3, Wout, bout,
        out, nb);
}

// round 17
// speedup vs baseline: 1.2527x; 1.2527x over previous
#include <cuda_runtime.h>
#include <cuda_fp16.h>

#define HID 128
#define NS  12
#define NW  14
#define PAIRS (NW/2)
#define THREADS (NW*32)
#define GRID 148
#define MROWS 16

typedef unsigned u32;

// ---- SMEM layout (bytes) ----
#define OFF_W1F 0
#define OFF_W1B 32768
#define OFF_W2F 65536
#define OFF_W2B 98304
#define OFF_W0F 131072
#define OFF_W0B 135168
#define OFF_CON 139264
#define OFF_PB  141568
#define PBSTRIDE 8256                // ACTa 4096 | ACTb 4096 | VX 64
#define SMEM_BYTES (OFF_PB + PAIRS*PBSTRIDE)   // 199360

// tanh.approx.f32: 1 MUFU op, err ~2^-11 (same order as fp16 rounding)
__device__ __forceinline__ float ftanh(float x)
{
    float y;
    asm("tanh.approx.f32 %0, %1;" : "=f"(y) : "f"(x));
    return y;
}
__device__ __forceinline__ u32 f2h2(float a, float b)
{
    __half2 h = __floats2half2_rn(a, b);
    return *(u32*)&h;
}
__device__ __forceinline__ float2 h22f2(u32 u)
{
    return __half22float2(*(__half2*)&u);
}
__device__ __forceinline__ void mma16816(float c[4], const u32* a, uint2 b)
{
    asm volatile(
        "mma.sync.aligned.m16n8k16.row.col.f32.f16.f16.f32 "
        "{%0,%1,%2,%3}, {%4,%5,%6,%7}, {%8,%9}, {%0,%1,%2,%3};\n"
        : "+f"(c[0]), "+f"(c[1]), "+f"(c[2]), "+f"(c[3])
        : "r"(a[0]), "r"(a[1]), "r"(a[2]), "r"(a[3]), "r"(b.x), "r"(b.y));
}
__device__ __forceinline__ void bar_pair(int id)
{
    asm volatile("bar.sync %0, 64;" :: "r"(id) : "memory");
}

// A-fill: own 8 nt slots from registers, foreign 8 from SMEM.
// OWN = this warp's nt base (0 or 8), compile-time so A indices stay constant.
template<int OWN>
__device__ __forceinline__ void fillA(u32* A, const u32* ownk,
                                      const uint2* ACT, int l)
{
    constexpr int FB = (OWN == 0) ? 8 : 0;
#pragma unroll
    for (int i = 0; i < 8; ++i) {
        A[2*(OWN+i)]   = ownk[2*i];
        A[2*(OWN+i)+1] = ownk[2*i+1];
    }
#pragma unroll
    for (int j = 0; j < 8; ++j) {
        uint2 v = ACT[(FB + j)*32 + l];
        A[2*(FB+j)]   = v.x;
        A[2*(FB+j)+1] = v.y;
    }
}

__global__ __launch_bounds__(THREADS, 1)
void mlp_kernel(const float* __restrict__ state,
                const float* __restrict__ safe_m, const float* __restrict__ safe_l,
                const float* __restrict__ W0, const float* __restrict__ b0,
                const float* __restrict__ W1, const float* __restrict__ b1,
                const float* __restrict__ W2, const float* __restrict__ b2,
                const float* __restrict__ W3, const float* __restrict__ b3,
                const float* __restrict__ Wout, const float* __restrict__ bout,
                float* __restrict__ out, int nb)
{
    extern __shared__ char smem[];
    uint2* W1F = (uint2*)(smem + OFF_W1F);
    uint2* W1B = (uint2*)(smem + OFF_W1B);
    uint2* W2F = (uint2*)(smem + OFF_W2F);
    uint2* W2B = (uint2*)(smem + OFF_W2B);
    uint2* W0F = (uint2*)(smem + OFF_W0F);
    uint2* W0B = (uint2*)(smem + OFF_W0B);
    float* CON = (float*)(smem + OFF_CON);
    float* PRT = (float*)(smem + OFF_PB);      // init-time scratch (R3/c3 partials)

    int tid = threadIdx.x;

    // ---- constants ----
    if (tid < HID) {
        CON[0   + tid] = b0[tid];
        CON[128 + tid] = b1[tid];
        CON[256 + tid] = b2[tid];
        PRT[384 + tid] = Wout[tid] * b3[tid];  // c3 partial
    }
    if (tid < NS) {
        float m = safe_m[tid], lo = safe_l[tid];
        CON[512 + tid] = 0.5f * (m + lo);
        CON[528 + tid] = 2.0f / (m - lo);
    }
    // ---- R3 partials: 3 slices x 128 threads (short chains, coalesced) ----
    if (tid < 384) {
        int h = tid & 127, sl = tid >> 7;
        int j0 = (sl * HID) / 3, j1 = ((sl + 1) * HID) / 3;
        float acc = 0.f;
#pragma unroll 4
        for (int j = j0; j < j1; ++j) acc = fmaf(Wout[j], W3[j*HID + h], acc);
        PRT[sl*128 + h] = acc;
    }

    // ---- build W1/W2 fragments directly from global (warm-L2 broadcast) ----
    for (int e = tid; e < 128*32; e += THREADS) {
        int T = e >> 5, lf = e & 31;
        int kt = T >> 4, nt = T & 15, qf = lf & 3, gf = lf >> 2;
        int n = 8*nt + gf, k = 16*kt + 2*qf;
        {
            float2 wlo = *(const float2*)&W1[n*HID + k];
            float2 whi = *(const float2*)&W1[n*HID + k + 8];
            uint2 uf; uf.x = f2h2(wlo.x, wlo.y); uf.y = f2h2(whi.x, whi.y);
            uint2 ub;
            ub.x = f2h2(W1[k*HID + n],     W1[(k+1)*HID + n]);
            ub.y = f2h2(W1[(k+8)*HID + n], W1[(k+9)*HID + n]);
            W1F[e] = uf; W1B[e] = ub;
        }
        {
            float2 wlo = *(const float2*)&W2[n*HID + k];
            float2 whi = *(const float2*)&W2[n*HID + k + 8];
            uint2 uf; uf.x = f2h2(wlo.x, wlo.y); uf.y = f2h2(whi.x, whi.y);
            uint2 ub;
            ub.x = f2h2(W2[k*HID + n],     W2[(k+1)*HID + n]);
            ub.y = f2h2(W2[(k+8)*HID + n], W2[(k+9)*HID + n]);
            W2F[e] = uf; W2B[e] = ub;
        }
    }
    for (int e = tid; e < 16*32; e += THREADS) {
        int T = e >> 5, lf = e & 31, qf = lf & 3, gf = lf >> 2;
        {   // W0F: fwd GEMM0, T = nt
            int n = 8*T + gf, k = 2*qf;
            uint2 u;
            u.x = f2h2(W0[n*NS + k], W0[n*NS + k + 1]);
            u.y = (qf < 2) ? f2h2(W0[n*NS + k + 8], W0[n*NS + k + 9]) : 0u;
            W0F[e] = u;
        }
        {   // W0B: final J, kt=T>>1, nt=T&1
            int kt = T >> 1, ntb = T & 1;
            int n = 8*ntb + gf, k = 16*kt + 2*qf;
            float w00 = 0.f, w01 = 0.f, w10 = 0.f, w11 = 0.f;
            if (n < NS) {
                w00 = W0[k*NS + n];     w01 = W0[(k+1)*NS + n];
                w10 = W0[(k+8)*NS + n]; w11 = W0[(k+9)*NS + n];
            }
            uint2 u; u.x = f2h2(w00, w01); u.y = f2h2(w10, w11);
            W0B[e] = u;
        }
    }
    __syncthreads();
    // combine R3 partials; c3 reduce
    if (tid < HID)
        CON[384 + tid] = PRT[tid] + PRT[128 + tid] + PRT[256 + tid];
    if (tid == 0) {
        float c = bout[0];
#pragma unroll 4
        for (int i = 0; i < HID; i += 4) {
            float4 p = *(const float4*)&PRT[384 + i];
            c += p.x + p.y + p.z + p.w;
        }
        CON[544] = c;
    }
    __syncthreads();

    int w = tid >> 5, l = tid & 31, q = l & 3, g = l >> 2;
    int pair = w >> 1, wa = w & 1;
    char* PB = smem + OFF_PB + pair*PBSTRIDE;
    uint2* ACTa = (uint2*)PB;             // [16 nt][32 lanes]
    uint2* ACTb = (uint2*)(PB + 4096);
    float* VX   = (float*)(PB + 8192);
    int barid = pair + 1;

    const float* B0S = CON;
    const float* B1S = CON + 128;
    const float* B2S = CON + 256;
    const float* R3S = CON + 384;
    const float* CENS = CON + 512;
    const float* INVS = CON + 528;

    int nt0 = 8*wa;                       // this warp's n-tile half

    int ntask = (nb + MROWS - 1) / MROWS;
    for (int task = blockIdx.x + GRID*pair; task < ntask; task += GRID*PAIRS) {
        int base = task * MROWS;
        int ra = base + g, rb = base + g + 8;
        bool oka = ra < nb, okb = rb < nb;

        u32 A[32];
        u32 V0k[16], V1k[16], gk[16];     // own-half V0 / V1 / current-g (fp16 pairs)
        float c[8][4];

        // ---- X load + normalize -> A[0..3] ----
        {
            float2 z2 = make_float2(0.f, 0.f);
            float2 xa = oka ? *(const float2*)&state[ra*NS + 2*q] : z2;
            float2 xb = okb ? *(const float2*)&state[rb*NS + 2*q] : z2;
            float2 xc = z2, xd = z2;
            float c0v = CENS[2*q], c1v = CENS[2*q+1];
            float i0v = INVS[2*q], i1v = INVS[2*q+1];
            xa.x = (xa.x - c0v)*i0v; xa.y = (xa.y - c1v)*i1v;
            xb.x = (xb.x - c0v)*i0v; xb.y = (xb.y - c1v)*i1v;
            if (q < 2) {
                if (oka) xc = *(const float2*)&state[ra*NS + 2*q + 8];
                if (okb) xd = *(const float2*)&state[rb*NS + 2*q + 8];
                float c2v = CENS[2*q+8], c3v = CENS[2*q+9];
                float i2v = INVS[2*q+8], i3v = INVS[2*q+9];
                xc.x = (xc.x - c2v)*i2v; xc.y = (xc.y - c3v)*i3v;
                xd.x = (xd.x - c2v)*i2v; xd.y = (xd.y - c3v)*i3v;
            }
            A[0] = f2h2(xa.x, xa.y);
            A[1] = f2h2(xb.x, xb.y);
            A[2] = f2h2(xc.x, xc.y);
            A[3] = f2h2(xd.x, xd.y);
        }

        // ---- G0: V0 = tanh(X*W0^T + b0) -> ACTa + V0k ----
#pragma unroll
        for (int i = 0; i < 8; ++i) {
            int nt = nt0 + i;
            float2 bp = *(const float2*)&B0S[8*nt + 2*q];
            c[i][0] = bp.x; c[i][1] = bp.y; c[i][2] = bp.x; c[i][3] = bp.y;
            mma16816(c[i], &A[0], W0F[nt*32 + l]);
        }
#pragma unroll
        for (int i = 0; i < 8; ++i) {
            uint2 u;
            u.x = f2h2(ftanh(c[i][0]), ftanh(c[i][1]));
            u.y = f2h2(ftanh(c[i][2]), ftanh(c[i][3]));
            ACTa[(nt0 + i)*32 + l] = u;
            V0k[2*i] = u.x; V0k[2*i+1] = u.y;
        }
        bar_pair(barid);                             // (1) ACTa complete

        // ---- G1: V1 = tanh(V0*W1^T + b1): own V0 from regs, foreign from ACTa ----
        if (wa == 0) fillA<0>(A, V0k, ACTa, l); else fillA<8>(A, V0k, ACTa, l);
#pragma unroll
        for (int i = 0; i < 8; ++i) {
            float2 bp = *(const float2*)&B1S[8*(nt0+i) + 2*q];
            c[i][0] = bp.x; c[i][1] = bp.y; c[i][2] = bp.x; c[i][3] = bp.y;
        }
#pragma unroll
        for (int kt = 0; kt < 8; ++kt)
#pragma unroll
            for (int i = 0; i < 8; ++i)
                mma16816(c[i], &A[kt*4], W1F[(kt*16 + nt0 + i)*32 + l]);
#pragma unroll
        for (int i = 0; i < 8; ++i) {
            uint2 u;
            u.x = f2h2(ftanh(c[i][0]), ftanh(c[i][1]));
            u.y = f2h2(ftanh(c[i][2]), ftanh(c[i][3]));
            ACTb[(nt0 + i)*32 + l] = u;
            V1k[2*i] = u.x; V1k[2*i+1] = u.y;
        }
        bar_pair(barid);                             // (2) ACTb complete

        // ---- G2: V2 = tanh(V1*W2^T + b2); vout partial; g2 -> ACTa + gk ----
        if (wa == 0) fillA<0>(A, V1k, ACTb, l); else fillA<8>(A, V1k, ACTb, l);
#pragma unroll
        for (int i = 0; i < 8; ++i) {
            float2 bp = *(const float2*)&B2S[8*(nt0+i) + 2*q];
            c[i][0] = bp.x; c[i][1] = bp.y; c[i][2] = bp.x; c[i][3] = bp.y;
        }
#pragma unroll
        for (int kt = 0; kt < 8; ++kt)
#pragma unroll
            for (int i = 0; i < 8; ++i)
                mma16816(c[i], &A[kt*4], W2F[(kt*16 + nt0 + i)*32 + l]);
        float vg = 0.f, vg8 = 0.f;
#pragma unroll
        for (int i = 0; i < 8; ++i) {
            int nt = nt0 + i;
            float2 r3p = *(const float2*)&R3S[8*nt + 2*q];
            float t0 = ftanh(c[i][0]), t1 = ftanh(c[i][1]);
            float t2 = ftanh(c[i][2]), t3 = ftanh(c[i][3]);
            vg  += r3p.x*t0 + r3p.y*t1;
            vg8 += r3p.x*t2 + r3p.y*t3;
            uint2 u;
            u.x = f2h2(r3p.x*(1.f - t0*t0), r3p.y*(1.f - t1*t1));
            u.y = f2h2(r3p.x*(1.f - t2*t2), r3p.y*(1.f - t3*t3));
            ACTa[nt*32 + l] = u;
            gk[2*i] = u.x; gk[2*i+1] = u.y;
        }
        vg  += __shfl_xor_sync(0xffffffffu, vg, 1);
        vg  += __shfl_xor_sync(0xffffffffu, vg, 2);
        vg8 += __shfl_xor_sync(0xffffffffu, vg8, 1);
        vg8 += __shfl_xor_sync(0xffffffffu, vg8, 2);
        if (wa == 1 && q == 0) { VX[g] = vg; VX[8+g] = vg8; }
        bar_pair(barid);                             // (3) g2 + VX complete
        if (wa == 0 && q == 0) {
            float c3 = CON[544];
            if (oka) out[ra*13] = vg + VX[g] + c3;
            if (okb) out[rb*13] = vg8 + VX[8+g] + c3;
        }

        // ---- B2: r1 = g2*W2 ; g1 = r1*(1-V1^2): own g2 from gk, foreign ACTa ----
        if (wa == 0) fillA<0>(A, gk, ACTa, l); else fillA<8>(A, gk, ACTa, l);
#pragma unroll
        for (int i = 0; i < 8; ++i) { c[i][0]=0.f; c[i][1]=0.f; c[i][2]=0.f; c[i][3]=0.f; }
#pragma unroll
        for (int kt = 0; kt < 8; ++kt)
#pragma unroll
            for (int i = 0; i < 8; ++i)
                mma16816(c[i], &A[kt*4], W2B[(kt*16 + nt0 + i)*32 + l]);
#pragma unroll
        for (int i = 0; i < 8; ++i) {
            float2 va = h22f2(V1k[2*i]), vb = h22f2(V1k[2*i+1]);
            uint2 u;
            u.x = f2h2(c[i][0]*(1.f - va.x*va.x), c[i][1]*(1.f - va.y*va.y));
            u.y = f2h2(c[i][2]*(1.f - vb.x*vb.x), c[i][3]*(1.f - vb.y*vb.y));
            ACTb[(nt0 + i)*32 + l] = u;
            gk[2*i] = u.x; gk[2*i+1] = u.y;
        }
        bar_pair(barid);                             // (4) g1 complete

        // ---- B1: r0 = g1*W1 ; g0 = r0*(1-V0^2): own g1 from gk, foreign ACTb ----
        if (wa == 0) fillA<0>(A, gk, ACTb, l); else fillA<8>(A, gk, ACTb, l);
#pragma unroll
        for (int i = 0; i < 8; ++i) { c[i][0]=0.f; c[i][1]=0.f; c[i][2]=0.f; c[i][3]=0.f; }
#pragma unroll
        for (int kt = 0; kt < 8; ++kt)
#pragma unroll
            for (int i = 0; i < 8; ++i)
                mma16816(c[i], &A[kt*4], W1B[(kt*16 + nt0 + i)*32 + l]);
#pragma unroll
        for (int i = 0; i < 8; ++i) {
            float2 va = h22f2(V0k[2*i]), vb = h22f2(V0k[2*i+1]);
            uint2 u;
            u.x = f2h2(c[i][0]*(1.f - va.x*va.x), c[i][1]*(1.f - va.y*va.y));
            u.y = f2h2(c[i][2]*(1.f - vb.x*vb.x), c[i][3]*(1.f - vb.y*vb.y));
            ACTa[(nt0 + i)*32 + l] = u;
            gk[2*i] = u.x; gk[2*i+1] = u.y;
        }
        bar_pair(barid);                             // (5) g0 complete

        // ---- J: g0*W0 -> [16x12]: own g0 from gk, foreign ACTa ----
        if (wa == 0) fillA<0>(A, gk, ACTa, l); else fillA<8>(A, gk, ACTa, l);
        {
            float cj[4] = {0.f, 0.f, 0.f, 0.f};
#pragma unroll
            for (int kt = 0; kt < 8; ++kt)
                mma16816(cj, &A[kt*4], W0B[(kt*2 + wa)*32 + l]);
            int cb = 8*wa + 2*q;
            if (cb < NS) {
                float iv0 = INVS[cb], iv1 = INVS[cb+1];
                if (oka) {
                    out[ra*13 + 1 + cb]     = cj[0]*iv0;
                    out[ra*13 + 1 + cb + 1] = cj[1]*iv1;
                }
                if (okb) {
                    out[rb*13 + 1 + cb]     = cj[2]*iv0;
                    out[rb*13 + 1 + cb + 1] = cj[3]*iv1;
                }
            }
        }
        bar_pair(barid);                             // (6) J reads done before next G0
    }
}

extern "C" void kernel_launch(void* const* d_in, const int* in_sizes, int n_in,
                              void* d_out, int out_size)
{
    const float* state  = (const float*)d_in[0];
    const float* safe_m = (const float*)d_in[1];
    const float* safe_l = (const float*)d_in[2];
    const float* W0     = (const float*)d_in[3];
    const float* b0     = (const float*)d_in[4];
    const float* W1     = (const float*)d_in[5];
    const float* b1     = (const float*)d_in[6];
    const float* W2     = (const float*)d_in[7];
    const float* b2     = (const float*)d_in[8];
    const float* W3     = (const float*)d_in[9];
    const float* b3     = (const float*)d_in[10];
    const float* Wout   = (const float*)d_in[11];
    const float* bout   = (const float*)d_in[12];
    float* out = (float*)d_out;

    int nb = in_sizes[0] / NS;

    cudaFuncSetAttribute(mlp_kernel, cudaFuncAttributeMaxDynamicSharedMemorySize,
                         SMEM_BYTES);

    mlp_kernel<<<GRID, THREADS, SMEM_BYTES>>>(
        state, safe_m, safe_l, W0, b0, W1, b1, W2, b2, W3, b3, Wout, bout,
        out, nb);
}